// round 16
// baseline (speedup 1.0000x reference)
#include <cuda_runtime.h>
#include <cuda_fp16.h>
#include <cstdint>

// ---------------------------------------------------------------------------
// GraphSage (eval) on GB300 — round 16: aggregation fused into the layer
// kernels as phase -1 (per-CTA gather -> hagg tile in smem T area; conv
// chunks 4-7 read A from T). hagg never touches GMEM.
// ---------------------------------------------------------------------------

#define NMAX 50000
#define EMAX 1000000
#define FDIM 256
#define PADC 304
#define SCAN_B 1024
#define MAXBLK 64

// fp16 buffers (zero-initialized; pad columns never written)
__device__ __align__(16) __half g_h16[NMAX * FDIM];
__device__ __align__(16) __half g_hb16[NMAX * FDIM];
__device__ __align__(16) __half g_tmp16[NMAX * PADC];
__device__ __align__(16) __half g_emb16[(NMAX + 1) * 64];
__device__ __align__(16) __half g_c16[NMAX * PADC];
__device__ __align__(16) __half g_we16[256 * 64];
__device__ __align__(16) __half g_wp1[304 * PADC];
__device__ __align__(16) __half g_wp2[256 * PADC];
__device__ __align__(16) __half g_wc16[3 * 256 * 512];
__device__ __align__(16) __half g_wo1[2 * 256 * 256];
__device__ __align__(16) __half g_wo2[2 * 256 * 256];
// CSR
__device__ int g_deg[NMAX];
__device__ int g_rowoff[NMAX + 1];
__device__ int g_cursor[NMAX];
__device__ int g_adj[EMAX];
__device__ int g_bsum[MAXBLK];
__device__ int g_boff[MAXBLK];

// ---------------------------------------------------------------------------
struct StreamPack {
    cudaStream_t s1, s2;
    cudaEvent_t ev[8];
    StreamPack() {
        cudaStreamCreateWithFlags(&s1, cudaStreamNonBlocking);
        cudaStreamCreateWithFlags(&s2, cudaStreamNonBlocking);
        for (int i = 0; i < 8; i++)
            cudaEventCreateWithFlags(&ev[i], cudaEventDisableTiming);
    }
};
static StreamPack g_sp;

// ---------------------------------------------------------------------------
__global__ void cvt_all_kernel(
    const float* emb, const float* content, const float* W_exp,
    const float* W_p1, const float* W_p2, const float* W_conv,
    const float* Wo1, const float* Wo2,
    __half* d_emb, __half* d_c, __half* d_we, __half* d_wp1, __half* d_wp2,
    __half* d_wc, __half* d_wo1, __half* d_wo2,
    int N, int NC, int ED, int F, int L)
{
    const int s0 = (N + 1) * ED;
    const int s1 = N * NC;
    const int s2 = F * ED;
    const int s3 = NC * NC;
    const int s4 = F * NC;
    const int s5 = L * F * 2 * F;
    const int s6 = (L - 1) * F * F;
    const int s7 = (L - 1) * F * F;
    const int total = s0 + s1 + s2 + s3 + s4 + s5 + s6 + s7;
    for (int i = blockIdx.x * blockDim.x + threadIdx.x; i < total;
         i += gridDim.x * blockDim.x) {
        int j = i;
        if (j < s0) { d_emb[j] = __float2half_rn(emb[j]); continue; }
        j -= s0;
        if (j < s1) {
            int r = j / NC, c = j - r * NC;
            d_c[r * PADC + c] = __float2half_rn(content[j]);
            continue;
        }
        j -= s1;
        if (j < s2) { d_we[j] = __float2half_rn(W_exp[j]); continue; }
        j -= s2;
        if (j < s3) {
            int r = j / NC, c = j - r * NC;
            d_wp1[r * PADC + c] = __float2half_rn(W_p1[j]);
            continue;
        }
        j -= s3;
        if (j < s4) {
            int r = j / NC, c = j - r * NC;
            d_wp2[r * PADC + c] = __float2half_rn(W_p2[j]);
            continue;
        }
        j -= s4;
        if (j < s5) { d_wc[j] = __float2half_rn(W_conv[j]); continue; }
        j -= s5;
        if (j < s6) { d_wo1[j] = __float2half_rn(Wo1[j]); continue; }
        j -= s6;
        d_wo2[j] = __float2half_rn(Wo2[j]);
    }
}

// ---------------------------------------------------------------------------
// CSR build
__global__ void zero_deg_kernel(int n) {
    int i = blockIdx.x * blockDim.x + threadIdx.x;
    if (i < n) g_deg[i] = 0;
}
__global__ void count_deg_kernel(const int* __restrict__ dst, int E) {
    int i = blockIdx.x * blockDim.x + threadIdx.x;
    int stride = gridDim.x * blockDim.x;
    for (; i < E; i += stride) atomicAdd(&g_deg[dst[i]], 1);
}
__global__ void scan_reduce_kernel(int n) {
    __shared__ int ws[32];
    int t = threadIdx.x;
    int i = blockIdx.x * SCAN_B + t;
    int v = (i < n) ? g_deg[i] : 0;
    #pragma unroll
    for (int o = 16; o > 0; o >>= 1) v += __shfl_xor_sync(0xffffffffu, v, o);
    if ((t & 31) == 0) ws[t >> 5] = v;
    __syncthreads();
    if (t < 32) {
        int x = (t < (SCAN_B / 32)) ? ws[t] : 0;
        #pragma unroll
        for (int o = 16; o > 0; o >>= 1) x += __shfl_xor_sync(0xffffffffu, x, o);
        if (t == 0) g_bsum[blockIdx.x] = x;
    }
}
__global__ void scan_offsets_kernel(int nb, int n) {
    int acc = 0;
    for (int b = 0; b < nb; b++) { g_boff[b] = acc; acc += g_bsum[b]; }
    g_rowoff[n] = acc;
}
__global__ void scan_final_kernel(int n) {
    __shared__ int ws[32];
    int t = threadIdx.x;
    int i = blockIdx.x * SCAN_B + t;
    int v = (i < n) ? g_deg[i] : 0;
    int x = v;
    #pragma unroll
    for (int o = 1; o < 32; o <<= 1) {
        int y = __shfl_up_sync(0xffffffffu, x, o);
        if ((t & 31) >= o) x += y;
    }
    if ((t & 31) == 31) ws[t >> 5] = x;
    __syncthreads();
    if (t < 32) {
        int w = (t < (SCAN_B / 32)) ? ws[t] : 0;
        int xx = w;
        #pragma unroll
        for (int o = 1; o < 32; o <<= 1) {
            int y = __shfl_up_sync(0xffffffffu, xx, o);
            if (t >= o) xx += y;
        }
        ws[t] = xx - w;
    }
    __syncthreads();
    if (i < n) {
        int excl = x - v + ws[t >> 5] + g_boff[blockIdx.x];
        g_rowoff[i] = excl;
        g_cursor[i] = excl;
    }
}
__global__ void scatter_kernel(const int* __restrict__ src,
                               const int* __restrict__ dst, int E) {
    int i = blockIdx.x * blockDim.x + threadIdx.x;
    int stride = gridDim.x * blockDim.x;
    for (; i < E; i += stride) {
        int p = atomicAdd(&g_cursor[dst[i]], 1);
        g_adj[p] = src[i];
    }
}

// ---------------------------------------------------------------------------
__device__ __forceinline__ void mma_f16(float* c, const uint32_t* a,
                                        const uint32_t* b) {
    asm volatile(
        "mma.sync.aligned.m16n8k16.row.col.f32.f16.f16.f32 "
        "{%0,%1,%2,%3}, {%4,%5,%6,%7}, {%8,%9}, {%0,%1,%2,%3};"
        : "+f"(c[0]), "+f"(c[1]), "+f"(c[2]), "+f"(c[3])
        : "r"(a[0]), "r"(a[1]), "r"(a[2]), "r"(a[3]), "r"(b[0]), "r"(b[1]));
}
__device__ __forceinline__ void ldsm4(uint32_t* r, uint32_t addr) {
    asm volatile("ldmatrix.sync.aligned.m8n8.x4.shared.b16 {%0,%1,%2,%3}, [%4];"
                 : "=r"(r[0]), "=r"(r[1]), "=r"(r[2]), "=r"(r[3]) : "r"(addr));
}
__device__ __forceinline__ void cp16(uint32_t dst, const void* src, int nbytes) {
    asm volatile("cp.async.cg.shared.global [%0], [%1], 16, %2;"
                 :: "r"(dst), "l"(src), "r"(nbytes) : "memory");
}
__device__ __forceinline__ void cp_commit() {
    asm volatile("cp.async.commit_group;" ::: "memory");
}
__device__ __forceinline__ void cp_wait1() {
    asm volatile("cp.async.wait_group 1;" ::: "memory");
}

#define GBM 128
#define GBN 128
#define GBK 64
#define TILE_BYTES 16384
#define STAGE_BYTES (2 * TILE_BYTES)
#define NSTAGE 3

extern __shared__ __align__(16) char sm_raw[];

// ---------------------------------------------------------------------------
// Generic fp16 GEMM: used for emb/p1/p2 prologue.
__global__ __launch_bounds__(256, 2)
void gemm_f16(const __half* __restrict__ A, int lda,
              const int* __restrict__ gidx,
              const __half* __restrict__ W, int ldw,
              const float* __restrict__ bias,
              const __half* __restrict__ addsrc16,
              __half* __restrict__ C16, int ldc,
              int M, int Ncols, int K, int act)
{
    const int tid = threadIdx.x;
    const int wid = tid >> 5;
    const int lane = tid & 31;
    const int bm = blockIdx.x * GBM;
    const int bn = blockIdx.y * GBN;
    const int warp_m = (wid >> 2) * 64;
    const int warp_n = (wid & 3) * 32;

    const int ldRow = tid >> 1;
    const int kHalf = tid & 1;

    const bool aValid = (bm + ldRow < M);
    int aR = aValid ? (bm + ldRow) : 0;
    if (gidx) aR = __ldg(&gidx[aValid ? bm + ldRow : 0]);
    const __half* aBase = A + (size_t)aR * lda;
    const bool bValid = (bn + ldRow < Ncols);
    const __half* bBase = W + (size_t)(bValid ? bn + ldRow : 0) * ldw;

    const uint32_t smemBase = (uint32_t)__cvta_generic_to_shared(sm_raw);
    const int nCh = (K + GBK - 1) / GBK;
    const int ldSwz = (ldRow & 7);

    float acc[4][4][4];
    #pragma unroll
    for (int mt = 0; mt < 4; mt++)
        #pragma unroll
        for (int nt = 0; nt < 4; nt++)
            #pragma unroll
            for (int j = 0; j < 4; j++) acc[mt][nt][j] = 0.f;

    auto issueStage = [&](int ch, int stage) {
        if (ch < nCh) {
            const uint32_t aDst = smemBase + stage * STAGE_BYTES + ldRow * 128;
            const uint32_t bDst = aDst + TILE_BYTES;
            #pragma unroll
            for (int j = 0; j < 4; j++) {
                const int c = kHalf * 4 + j;
                const int k = ch * GBK + c * 8;
                const int rem = K - k;
                const int nb = (rem >= 8) ? 16 : (rem > 0 ? rem * 2 : 0);
                const uint32_t sw = (uint32_t)((c ^ ldSwz) << 4);
                cp16(aDst + sw, aBase + k, aValid ? nb : 0);
                cp16(bDst + sw, bBase + k, bValid ? nb : 0);
            }
        }
        cp_commit();
    };

    const int l8 = lane & 7;
    int aRowB[4], aSwz[4];
    #pragma unroll
    for (int mt = 0; mt < 4; mt++) {
        int row = warp_m + mt * 16 + l8 + ((lane >> 3) & 1) * 8;
        aRowB[mt] = row * 128;
        aSwz[mt] = row & 7;
    }
    const int aColAdd = lane >> 4;
    int bRowB[2], bSwz[2];
    #pragma unroll
    for (int pr = 0; pr < 2; pr++) {
        int row = warp_n + pr * 16 + l8 + ((lane >> 4) & 1) * 8;
        bRowB[pr] = row * 128;
        bSwz[pr] = row & 7;
    }
    const int bColAdd = (lane >> 3) & 1;

    auto computeStage = [&](int stage) {
        const uint32_t aTile = smemBase + stage * STAGE_BYTES;
        const uint32_t bTile = aTile + TILE_BYTES;
        #pragma unroll
        for (int ks = 0; ks < 4; ks++) {
            uint32_t af[4][4], bf[4][2];
            const int colA = ks * 2 + aColAdd;
            #pragma unroll
            for (int mt = 0; mt < 4; mt++)
                ldsm4(af[mt], aTile + aRowB[mt] + ((colA ^ aSwz[mt]) << 4));
            const int colB = ks * 2 + bColAdd;
            #pragma unroll
            for (int pr = 0; pr < 2; pr++) {
                uint32_t r[4];
                ldsm4(r, bTile + bRowB[pr] + ((colB ^ bSwz[pr]) << 4));
                bf[2 * pr][0] = r[0]; bf[2 * pr][1] = r[1];
                bf[2 * pr + 1][0] = r[2]; bf[2 * pr + 1][1] = r[3];
            }
            #pragma unroll
            for (int mt = 0; mt < 4; mt++)
                #pragma unroll
                for (int nt = 0; nt < 4; nt++)
                    mma_f16(acc[mt][nt], af[mt], bf[nt]);
        }
    };

    issueStage(0, 0);
    issueStage(1, 1);
    for (int ch = 0; ch < nCh; ch++) {
        cp_wait1();
        __syncthreads();
        computeStage(ch % NSTAGE);
        issueStage(ch + 2, (ch + 2) % NSTAGE);
    }

    #pragma unroll
    for (int mt = 0; mt < 4; mt++) {
        int row = bm + warp_m + mt * 16 + (lane >> 2);
        #pragma unroll
        for (int nt = 0; nt < 4; nt++) {
            int col = bn + warp_n + nt * 8 + 2 * (lane & 3);
            if (col >= Ncols) continue;
            float b0 = __ldg(&bias[col]);
            float b1 = __ldg(&bias[col + 1]);
            #pragma unroll
            for (int half = 0; half < 2; half++) {
                int r = row + half * 8;
                if (r >= M) continue;
                float v0 = acc[mt][nt][half * 2 + 0] + b0;
                float v1 = acc[mt][nt][half * 2 + 1] + b1;
                if (act) {
                    v0 = (v0 > 0.f) ? v0 : 0.1f * v0;
                    v1 = (v1 > 0.f) ? v1 : 0.1f * v1;
                }
                if (addsrc16) {
                    float2 s = __half22float2(
                        *(const __half2*)&addsrc16[(size_t)r * ldc + col]);
                    v0 += s.x; v1 += s.y;
                }
                *(__half2*)&C16[(size_t)r * ldc + col] =
                    __floats2half2_rn(v0, v1);
            }
        }
    }
}

// ---------------------------------------------------------------------------
// Fused layer machinery (128x256 full-row tile, 512 threads, 16 warps 32x64).
// Phase -1: per-CTA aggregation of this tile's 128 nodes into T smem (hagg).
#define FTH 512
#define F_AB 16384
#define F_BB 32768
#define F_ST (F_AB + F_BB)
#define F_RING (3 * F_ST)             // 147456
#define F_TOFF F_RING
#define F_SMEM (F_RING + 65536)       // 212992

// gather this CTA's hagg tile into T (chunk-major swizzled, ldmatrix layout)
__device__ __forceinline__ void gather_hagg_to_T(
    const __half* __restrict__ h, int bm, int M, int tid, int wid, int lane)
{
    if (bm + 128 > M) {  // partial tile: zero T so garbage can't appear
        uint4 z = make_uint4(0, 0, 0, 0);
        for (int i = tid; i < 4096; i += FTH)
            ((uint4*)(sm_raw + F_TOFF))[i] = z;
        __syncthreads();
    }
    const int pairId = wid >> 1;                  // 0..7, 16 nodes each
    const int jj = ((wid & 1) << 5) | lane;       // 0..63, owns cols jj*4..+3
    const int col = jj * 4;
    const int chunk = col >> 6;
    const int c16 = (col >> 3) & 7;
    for (int nn = 0; nn < 16; nn++) {
        int node = bm + pairId * 16 + nn;
        if (node >= M) break;
        int beg = g_rowoff[node], end = g_rowoff[node + 1];
        float a0 = 0.f, a1 = 0.f, a2 = 0.f, a3 = 0.f;
        int e = beg;
        for (; e + 3 < end; e += 4) {
            int s0 = g_adj[e], s1 = g_adj[e + 1],
                s2 = g_adj[e + 2], s3 = g_adj[e + 3];
            uint2 u0 = *(const uint2*)&h[(size_t)s0 * FDIM + col];
            uint2 u1 = *(const uint2*)&h[(size_t)s1 * FDIM + col];
            uint2 u2 = *(const uint2*)&h[(size_t)s2 * FDIM + col];
            uint2 u3 = *(const uint2*)&h[(size_t)s3 * FDIM + col];
            float2 p;
            p = __half22float2(*(const __half2*)&u0.x); a0 += p.x; a1 += p.y;
            p = __half22float2(*(const __half2*)&u0.y); a2 += p.x; a3 += p.y;
            p = __half22float2(*(const __half2*)&u1.x); a0 += p.x; a1 += p.y;
            p = __half22float2(*(const __half2*)&u1.y); a2 += p.x; a3 += p.y;
            p = __half22float2(*(const __half2*)&u2.x); a0 += p.x; a1 += p.y;
            p = __half22float2(*(const __half2*)&u2.y); a2 += p.x; a3 += p.y;
            p = __half22float2(*(const __half2*)&u3.x); a0 += p.x; a1 += p.y;
            p = __half22float2(*(const __half2*)&u3.y); a2 += p.x; a3 += p.y;
        }
        for (; e < end; e++) {
            int s0 = g_adj[e];
            uint2 u0 = *(const uint2*)&h[(size_t)s0 * FDIM + col];
            float2 p;
            p = __half22float2(*(const __half2*)&u0.x); a0 += p.x; a1 += p.y;
            p = __half22float2(*(const __half2*)&u0.y); a2 += p.x; a3 += p.y;
        }
        int d = end - beg;
        float inv = 1.0f / (float)(d > 1 ? d : 1);
        int lr = node - bm;
        uint32_t off = (uint32_t)(F_TOFF + chunk * 16384 + lr * 128 +
                                  ((c16 ^ (lr & 7)) << 4) + (col & 7) * 2);
        uint2 o;
        *(__half2*)&o.x = __floats2half2_rn(a0 * inv, a1 * inv);
        *(__half2*)&o.y = __floats2half2_rn(a2 * inv, a3 * inv);
        *(uint2*)(sm_raw + off) = o;
    }
    __syncthreads();  // T (hagg tile) visible to all warps
}

__global__ __launch_bounds__(FTH, 1)
void fused_layer(const __half* __restrict__ hin,
                 const __half* __restrict__ Wc, const float* __restrict__ bc,
                 const __half* __restrict__ Wo1, const float* __restrict__ bo1,
                 const __half* __restrict__ Wo2, const float* __restrict__ bo2,
                 __half* __restrict__ hout, int M)
{
    const int tid = threadIdx.x;
    const int wid = tid >> 5;
    const int lane = tid & 31;
    const int bm = blockIdx.x * 128;
    const int warp_m = (wid >> 2) * 32;
    const int warp_n = (wid & 3) * 64;

    const int aRow = tid >> 2, aq = tid & 3;
    const int bRow = tid >> 1, bh = tid & 1;
    const bool aValid = (bm + aRow < M);
    const __half* aLo = hin + (size_t)(aValid ? bm + aRow : 0) * 256;
    const int aSwzL = aRow & 7, bSwzL = bRow & 7;

    const uint32_t smemBase = (uint32_t)__cvta_generic_to_shared(sm_raw);

    const int l8 = lane & 7;
    int aRowB[2], aSwz[2];
    #pragma unroll
    for (int mt = 0; mt < 2; mt++) {
        int row = warp_m + mt * 16 + l8 + ((lane >> 3) & 1) * 8;
        aRowB[mt] = row * 128;
        aSwz[mt] = row & 7;
    }
    const int aColAdd = lane >> 4;
    int bRowB[4], bSwz[4];
    #pragma unroll
    for (int pr = 0; pr < 4; pr++) {
        int row = warp_n + pr * 16 + l8 + ((lane >> 4) & 1) * 8;
        bRowB[pr] = row * 128;
        bSwz[pr] = row & 7;
    }
    const int bColAdd = (lane >> 3) & 1;

    float acc[2][8][4];
    auto zacc = [&] {
        #pragma unroll
        for (int mt = 0; mt < 2; mt++)
            #pragma unroll
            for (int nt = 0; nt < 8; nt++)
                #pragma unroll
                for (int j = 0; j < 4; j++) acc[mt][nt][j] = 0.f;
    };

    // conv: A cp.async only for h-half chunks (0-3); B for all 8 chunks
    auto issueConv = [&](int ch) {
        const int stage = ch % 3;
        if (ch < 8) {
            if (ch < 4) {
                const uint32_t aDst = smemBase + stage * F_ST + aRow * 128;
                #pragma unroll
                for (int j = 0; j < 2; j++) {
                    const int c = aq * 2 + j;
                    const int k = ch * 64 + c * 8;
                    cp16(aDst + ((c ^ aSwzL) << 4), aLo + k, aValid ? 16 : 0);
                }
            }
            const uint32_t bDst = smemBase + stage * F_ST + F_AB + bRow * 128;
            #pragma unroll
            for (int j = 0; j < 4; j++) {
                const int c = bh * 4 + j;
                cp16(bDst + ((c ^ bSwzL) << 4),
                     Wc + (size_t)bRow * 512 + ch * 64 + c * 8, 16);
            }
        }
        cp_commit();
    };
    auto issueB = [&](const __half* W, int ch) {
        const int stage = ch % 3;
        if (ch < 4) {
            const uint32_t bDst = smemBase + stage * F_ST + F_AB + bRow * 128;
            #pragma unroll
            for (int j = 0; j < 4; j++) {
                const int c = bh * 4 + j;
                cp16(bDst + ((c ^ bSwzL) << 4),
                     W + (size_t)bRow * 256 + ch * 64 + c * 8, 16);
            }
        }
        cp_commit();
    };

    auto compute = [&](uint32_t aTile, uint32_t bTile) {
        #pragma unroll
        for (int ks = 0; ks < 4; ks++) {
            uint32_t af[2][4], bf[8][2];
            const int colA = ks * 2 + aColAdd;
            #pragma unroll
            for (int mt = 0; mt < 2; mt++)
                ldsm4(af[mt], aTile + aRowB[mt] + ((colA ^ aSwz[mt]) << 4));
            const int colB = ks * 2 + bColAdd;
            #pragma unroll
            for (int pr = 0; pr < 4; pr++) {
                uint32_t r[4];
                ldsm4(r, bTile + bRowB[pr] + ((colB ^ bSwz[pr]) << 4));
                bf[2 * pr][0] = r[0]; bf[2 * pr][1] = r[1];
                bf[2 * pr + 1][0] = r[2]; bf[2 * pr + 1][1] = r[3];
            }
            #pragma unroll
            for (int mt = 0; mt < 2; mt++)
                #pragma unroll
                for (int nt = 0; nt < 8; nt++)
                    mma_f16(acc[mt][nt], af[mt], bf[nt]);
        }
    };

    auto storeT = [&](int mt, int nt, int half, float v0, float v1) {
        int lr = warp_m + mt * 16 + (lane >> 2) + half * 8;
        int col = warp_n + nt * 8 + 2 * (lane & 3);
        int chunk = col >> 6;
        int c16 = (col >> 3) & 7;
        uint32_t off = (uint32_t)(F_TOFF + chunk * 16384 + lr * 128 +
                                  ((c16 ^ (lr & 7)) << 4) + (col & 7) * 2);
        *(__half2*)(sm_raw + off) = __floats2half2_rn(v0, v1);
    };

    // phase -1: aggregate this tile's hagg into T
    gather_hagg_to_T(hin, bm, M, tid, wid, lane);

    // phase 0: conv (K=512); chunks 4-7 read A from T (hagg tile)
    zacc();
    issueConv(0); issueConv(1);
    for (int ch = 0; ch < 8; ch++) {
        cp_wait1();
        __syncthreads();
        uint32_t aTile = (ch < 4) ? (smemBase + (ch % 3) * F_ST)
                                  : (smemBase + F_TOFF + (ch - 4) * 16384);
        compute(aTile, smemBase + (ch % 3) * F_ST + F_AB);
        issueConv(ch + 2);
    }
    __syncthreads();

    float ssl[2][2] = {{0.f, 0.f}, {0.f, 0.f}};
    #pragma unroll
    for (int mt = 0; mt < 2; mt++)
        #pragma unroll
        for (int nt = 0; nt < 8; nt++) {
            int col = warp_n + nt * 8 + 2 * (lane & 3);
            float b0 = __ldg(&bc[col]);
            float b1 = __ldg(&bc[col + 1]);
            #pragma unroll
            for (int half = 0; half < 2; half++) {
                float v0 = acc[mt][nt][half * 2 + 0] + b0;
                float v1 = acc[mt][nt][half * 2 + 1] + b1;
                v0 = (v0 > 0.f) ? v0 : 0.1f * v0;
                v1 = (v1 > 0.f) ? v1 : 0.1f * v1;
                acc[mt][nt][half * 2 + 0] = v0;
                acc[mt][nt][half * 2 + 1] = v1;
                ssl[mt][half] += v0 * v0 + v1 * v1;
            }
        }
    #pragma unroll
    for (int mt = 0; mt < 2; mt++)
        #pragma unroll
        for (int half = 0; half < 2; half++) {
            float s = ssl[mt][half];
            s += __shfl_xor_sync(0xffffffffu, s, 1);
            s += __shfl_xor_sync(0xffffffffu, s, 2);
            ssl[mt][half] = s;
        }
    float* part = (float*)sm_raw;
    float* invArr = (float*)(sm_raw + 2048);
    if ((lane & 3) == 0) {
        #pragma unroll
        for (int mt = 0; mt < 2; mt++)
            #pragma unroll
            for (int half = 0; half < 2; half++) {
                int lr = warp_m + mt * 16 + (lane >> 2) + half * 8;
                part[lr * 4 + (wid & 3)] = ssl[mt][half];
            }
    }
    __syncthreads();
    if (tid < 128) {
        float s = part[tid * 4] + part[tid * 4 + 1] +
                  part[tid * 4 + 2] + part[tid * 4 + 3];
        invArr[tid] = 1.0f / fmaxf(sqrtf(s), 1e-6f);
    }
    __syncthreads();
    float invs[2][2];
    #pragma unroll
    for (int mt = 0; mt < 2; mt++)
        #pragma unroll
        for (int half = 0; half < 2; half++)
            invs[mt][half] = invArr[warp_m + mt * 16 + (lane >> 2) + half * 8];
    #pragma unroll
    for (int mt = 0; mt < 2; mt++)
        #pragma unroll
        for (int nt = 0; nt < 8; nt++)
            #pragma unroll
            for (int half = 0; half < 2; half++)
                storeT(mt, nt, half, acc[mt][nt][half * 2], acc[mt][nt][half * 2 + 1]);
    issueB(Wo1, 0); issueB(Wo1, 1);
    __syncthreads();

    // phase 1: Wo1
    zacc();
    for (int ch = 0; ch < 4; ch++) {
        cp_wait1();
        __syncthreads();
        compute(smemBase + F_TOFF + ch * 16384,
                smemBase + (ch % 3) * F_ST + F_AB);
        issueB(Wo1, ch + 2);
    }
    __syncthreads();
    #pragma unroll
    for (int mt = 0; mt < 2; mt++)
        #pragma unroll
        for (int nt = 0; nt < 8; nt++) {
            int col = warp_n + nt * 8 + 2 * (lane & 3);
            float b0 = __ldg(&bo1[col]);
            float b1 = __ldg(&bo1[col + 1]);
            #pragma unroll
            for (int half = 0; half < 2; half++) {
                float v0 = acc[mt][nt][half * 2 + 0] * invs[mt][half] + b0;
                float v1 = acc[mt][nt][half * 2 + 1] * invs[mt][half] + b1;
                v0 = (v0 > 0.f) ? v0 : 0.1f * v0;
                v1 = (v1 > 0.f) ? v1 : 0.1f * v1;
                storeT(mt, nt, half, v0, v1);
            }
        }
    issueB(Wo2, 0); issueB(Wo2, 1);
    __syncthreads();

    // phase 2: Wo2
    zacc();
    for (int ch = 0; ch < 4; ch++) {
        cp_wait1();
        __syncthreads();
        compute(smemBase + F_TOFF + ch * 16384,
                smemBase + (ch % 3) * F_ST + F_AB);
        issueB(Wo2, ch + 2);
    }
    #pragma unroll
    for (int mt = 0; mt < 2; mt++) {
        #pragma unroll
        for (int half = 0; half < 2; half++) {
            int r = bm + warp_m + mt * 16 + (lane >> 2) + half * 8;
            if (r >= M) continue;
            #pragma unroll
            for (int nt = 0; nt < 8; nt++) {
                int col = warp_n + nt * 8 + 2 * (lane & 3);
                float v0 = acc[mt][nt][half * 2 + 0] + __ldg(&bo2[col]);
                float v1 = acc[mt][nt][half * 2 + 1] + __ldg(&bo2[col + 1]);
                *(__half2*)&hout[(size_t)r * 256 + col] =
                    __floats2half2_rn(v0, v1);
            }
        }
    }
}

// ---------------------------------------------------------------------------
// Fused FINAL layer: out = l2norm_row([h|hagg] @ Wc^T + bc), fp32 out.
__global__ __launch_bounds__(FTH, 1)
void fused_final(const __half* __restrict__ hin,
                 const __half* __restrict__ Wc, const float* __restrict__ bc,
                 float* __restrict__ out, int M)
{
    const int tid = threadIdx.x;
    const int wid = tid >> 5;
    const int lane = tid & 31;
    const int bm = blockIdx.x * 128;
    const int warp_m = (wid >> 2) * 32;
    const int warp_n = (wid & 3) * 64;

    const int aRow = tid >> 2, aq = tid & 3;
    const int bRow = tid >> 1, bh = tid & 1;
    const bool aValid = (bm + aRow < M);
    const __half* aLo = hin + (size_t)(aValid ? bm + aRow : 0) * 256;
    const int aSwzL = aRow & 7, bSwzL = bRow & 7;

    const uint32_t smemBase = (uint32_t)__cvta_generic_to_shared(sm_raw);

    const int l8 = lane & 7;
    int aRowB[2], aSwz[2];
    #pragma unroll
    for (int mt = 0; mt < 2; mt++) {
        int row = warp_m + mt * 16 + l8 + ((lane >> 3) & 1) * 8;
        aRowB[mt] = row * 128;
        aSwz[mt] = row & 7;
    }
    const int aColAdd = lane >> 4;
    int bRowB[4], bSwz[4];
    #pragma unroll
    for (int pr = 0; pr < 4; pr++) {
        int row = warp_n + pr * 16 + l8 + ((lane >> 4) & 1) * 8;
        bRowB[pr] = row * 128;
        bSwz[pr] = row & 7;
    }
    const int bColAdd = (lane >> 3) & 1;

    float acc[2][8][4];
    #pragma unroll
    for (int mt = 0; mt < 2; mt++)
        #pragma unroll
        for (int nt = 0; nt < 8; nt++)
            #pragma unroll
            for (int j = 0; j < 4; j++) acc[mt][nt][j] = 0.f;

    auto issueConv = [&](int ch) {
        const int stage = ch % 3;
        if (ch < 8) {
            if (ch < 4) {
                const uint32_t aDst = smemBase + stage * F_ST + aRow * 128;
                #pragma unroll
                for (int j = 0; j < 2; j++) {
                    const int c = aq * 2 + j;
                    const int k = ch * 64 + c * 8;
                    cp16(aDst + ((c ^ aSwzL) << 4), aLo + k, aValid ? 16 : 0);
                }
            }
            const uint32_t bDst = smemBase + stage * F_ST + F_AB + bRow * 128;
            #pragma unroll
            for (int j = 0; j < 4; j++) {
                const int c = bh * 4 + j;
                cp16(bDst + ((c ^ bSwzL) << 4),
                     Wc + (size_t)bRow * 512 + ch * 64 + c * 8, 16);
            }
        }
        cp_commit();
    };

    auto compute = [&](uint32_t aTile, uint32_t bTile) {
        #pragma unroll
        for (int ks = 0; ks < 4; ks++) {
            uint32_t af[2][4], bf[8][2];
            const int colA = ks * 2 + aColAdd;
            #pragma unroll
            for (int mt = 0; mt < 2; mt++)
                ldsm4(af[mt], aTile + aRowB[mt] + ((colA ^ aSwz[mt]) << 4));
            const int colB = ks * 2 + bColAdd;
            #pragma unroll
            for (int pr = 0; pr < 4; pr++) {
                uint32_t r[4];
                ldsm4(r, bTile + bRowB[pr] + ((colB ^ bSwz[pr]) << 4));
                bf[2 * pr][0] = r[0]; bf[2 * pr][1] = r[1];
                bf[2 * pr + 1][0] = r[2]; bf[2 * pr + 1][1] = r[3];
            }
            #pragma unroll
            for (int mt = 0; mt < 2; mt++)
                #pragma unroll
                for (int nt = 0; nt < 8; nt++)
                    mma_f16(acc[mt][nt], af[mt], bf[nt]);
        }
    };

    // phase -1: aggregate hagg tile into T
    gather_hagg_to_T(hin, bm, M, tid, wid, lane);

    issueConv(0); issueConv(1);
    for (int ch = 0; ch < 8; ch++) {
        cp_wait1();
        __syncthreads();
        uint32_t aTile = (ch < 4) ? (smemBase + (ch % 3) * F_ST)
                                  : (smemBase + F_TOFF + (ch - 4) * 16384);
        compute(aTile, smemBase + (ch % 3) * F_ST + F_AB);
        issueConv(ch + 2);
    }
    __syncthreads();

    // epilogue: bias (no act), row sumsq in-CTA, write normalized fp32
    float ssl[2][2] = {{0.f, 0.f}, {0.f, 0.f}};
    #pragma unroll
    for (int mt = 0; mt < 2; mt++)
        #pragma unroll
        for (int nt = 0; nt < 8; nt++) {
            int col = warp_n + nt * 8 + 2 * (lane & 3);
            float b0 = __ldg(&bc[col]);
            float b1 = __ldg(&bc[col + 1]);
            #pragma unroll
            for (int half = 0; half < 2; half++) {
                float v0 = acc[mt][nt][half * 2 + 0] + b0;
                float v1 = acc[mt][nt][half * 2 + 1] + b1;
                acc[mt][nt][half * 2 + 0] = v0;
                acc[mt][nt][half * 2 + 1] = v1;
                ssl[mt][half] += v0 * v0 + v1 * v1;
            }
        }
    #pragma unroll
    for (int mt = 0; mt < 2; mt++)
        #pragma unroll
        for (int half = 0; half < 2; half++) {
            float s = ssl[mt][half];
            s += __shfl_xor_sync(0xffffffffu, s, 1);
            s += __shfl_xor_sync(0xffffffffu, s, 2);
            ssl[mt][half] = s;
        }
    float* part = (float*)sm_raw;
    float* invArr = (float*)(sm_raw + 2048);
    if ((lane & 3) == 0) {
        #pragma unroll
        for (int mt = 0; mt < 2; mt++)
            #pragma unroll
            for (int half = 0; half < 2; half++) {
                int lr = warp_m + mt * 16 + (lane >> 2) + half * 8;
                part[lr * 4 + (wid & 3)] = ssl[mt][half];
            }
    }
    __syncthreads();
    if (tid < 128) {
        float s = part[tid * 4] + part[tid * 4 + 1] +
                  part[tid * 4 + 2] + part[tid * 4 + 3];
        invArr[tid] = 1.0f / fmaxf(sqrtf(s), 1e-6f);
    }
    __syncthreads();
    #pragma unroll
    for (int mt = 0; mt < 2; mt++) {
        #pragma unroll
        for (int half = 0; half < 2; half++) {
            int lr = warp_m + mt * 16 + (lane >> 2) + half * 8;
            int r = bm + lr;
            if (r >= M) continue;
            float inv = invArr[lr];
            #pragma unroll
            for (int nt = 0; nt < 8; nt++) {
                int col = warp_n + nt * 8 + 2 * (lane & 3);
                *(float2*)&out[(size_t)r * 256 + col] =
                    make_float2(acc[mt][nt][half * 2] * inv,
                                acc[mt][nt][half * 2 + 1] * inv);
            }
        }
    }
}

// ---------------------------------------------------------------------------
extern "C" void kernel_launch(void* const* d_in, const int* in_sizes, int n_in,
                              void* d_out, int out_size) {
    const int*   node_ids = (const int*)  d_in[0];
    const float* content  = (const float*)d_in[1];
    const int*   src      = (const int*)  d_in[2];
    const int*   dst      = (const int*)  d_in[3];
    const float* emb      = (const float*)d_in[4];
    const float* W_exp    = (const float*)d_in[5];
    const float* b_exp    = (const float*)d_in[6];
    const float* W_p1     = (const float*)d_in[7];
    const float* b_p1     = (const float*)d_in[8];
    const float* W_p2     = (const float*)d_in[9];
    const float* b_p2     = (const float*)d_in[10];
    const float* W_conv   = (const float*)d_in[11];
    const float* b_conv   = (const float*)d_in[12];
    const float* Wo1      = (const float*)d_in[13];
    const float* bo1      = (const float*)d_in[14];
    const float* Wo2      = (const float*)d_in[15];
    const float* bo2      = (const float*)d_in[16];
    float* out = (float*)d_out;

    const int N  = in_sizes[0];
    const int E  = in_sizes[2];
    const int NC = in_sizes[1] / N;                 // 300
    const int ED = in_sizes[4] / (N + 1);           // 64
    const int F  = in_sizes[5] / ED;                // 256
    const int L  = in_sizes[11] / (F * 2 * F);      // 3

    __half *p_h16, *p_hb16, *p_tmp16, *p_emb16, *p_c16;
    __half *p_we, *p_wp1, *p_wp2, *p_wc, *p_wo1, *p_wo2;
    cudaGetSymbolAddress((void**)&p_h16, g_h16);
    cudaGetSymbolAddress((void**)&p_hb16, g_hb16);
    cudaGetSymbolAddress((void**)&p_tmp16, g_tmp16);
    cudaGetSymbolAddress((void**)&p_emb16, g_emb16);
    cudaGetSymbolAddress((void**)&p_c16, g_c16);
    cudaGetSymbolAddress((void**)&p_we, g_we16);
    cudaGetSymbolAddress((void**)&p_wp1, g_wp1);
    cudaGetSymbolAddress((void**)&p_wp2, g_wp2);
    cudaGetSymbolAddress((void**)&p_wc, g_wc16);
    cudaGetSymbolAddress((void**)&p_wo1, g_wo1);
    cudaGetSymbolAddress((void**)&p_wo2, g_wo2);

    const int SMEM = NSTAGE * STAGE_BYTES;  // 98304
    cudaFuncSetAttribute(gemm_f16, cudaFuncAttributeMaxDynamicSharedMemorySize, SMEM);
    cudaFuncSetAttribute(fused_layer, cudaFuncAttributeMaxDynamicSharedMemorySize, F_SMEM);
    cudaFuncSetAttribute(fused_final, cudaFuncAttributeMaxDynamicSharedMemorySize, F_SMEM);

    cudaStream_t s1 = g_sp.s1, s2 = g_sp.s2;
    cudaEvent_t* ev = g_sp.ev;

    // ---- fork CSR chain to s1 ----
    cudaEventRecord(ev[0], 0);
    cudaStreamWaitEvent(s1, ev[0], 0);
    const int nb = (N + SCAN_B - 1) / SCAN_B;
    zero_deg_kernel<<<(N + 255) / 256, 256, 0, s1>>>(N);
    count_deg_kernel<<<1024, 256, 0, s1>>>(dst, E);
    scan_reduce_kernel<<<nb, SCAN_B, 0, s1>>>(N);
    scan_offsets_kernel<<<1, 1, 0, s1>>>(nb, N);
    scan_final_kernel<<<nb, SCAN_B, 0, s1>>>(N);
    scatter_kernel<<<1024, 256, 0, s1>>>(src, dst, E);
    cudaEventRecord(ev[1], s1);

    // ---- conversions on stream0 ----
    cvt_all_kernel<<<2048, 256>>>(emb, content, W_exp, W_p1, W_p2, W_conv,
                                  Wo1, Wo2, p_emb16, p_c16, p_we, p_wp1,
                                  p_wp2, p_wc, p_wo1, p_wo2, N, NC, ED, F, L);

    const int gmx = (N + GBM - 1) / GBM;
    auto gy = [](int n) { return (n + GBN - 1) / GBN; };

    // ---- emb GEMM on s2 -> fp16 scratch (hb16) ----
    cudaEventRecord(ev[2], 0);
    cudaStreamWaitEvent(s2, ev[2], 0);
    gemm_f16<<<dim3(gmx, gy(F)), 256, SMEM, s2>>>(
        p_emb16, ED, node_ids, p_we, ED, b_exp, nullptr,
        p_hb16, F, N, F, ED, 1);
    cudaEventRecord(ev[3], s2);

    gemm_f16<<<dim3(gmx, gy(NC)), 256, SMEM>>>(
        p_c16, PADC, nullptr, p_wp1, PADC, b_p1, nullptr,
        p_tmp16, PADC, N, NC, PADC, 1);
    cudaStreamWaitEvent(0, ev[3], 0);
    gemm_f16<<<dim3(gmx, gy(F)), 256, SMEM>>>(
        p_tmp16, PADC, nullptr, p_wp2, PADC, b_p2, p_hb16,
        p_h16, F, N, F, PADC, 1);

    cudaStreamWaitEvent(0, ev[1], 0);

    // ---- layers (h ping-pong between h16 and hb16; agg fused in-kernel) ----
    __half* hbuf[2] = {p_h16, p_hb16};
    int cur = 0;
    for (int i = 0; i < L; i++) {
        if (i < L - 1) {
            fused_layer<<<gmx, FTH, F_SMEM>>>(
                hbuf[cur],
                p_wc + (size_t)i * F * 2 * F, b_conv + (size_t)i * F,
                p_wo1 + (size_t)i * F * F, bo1 + (size_t)i * F,
                p_wo2 + (size_t)i * F * F, bo2 + (size_t)i * F,
                hbuf[1 - cur], N);
            cur ^= 1;
        } else {
            fused_final<<<gmx, FTH, F_SMEM>>>(
                hbuf[cur],
                p_wc + (size_t)i * F * 2 * F, b_conv + (size_t)i * F,
                out, N);
        }
    }
}

// round 17
// speedup vs baseline: 1.3550x; 1.3550x over previous
#include <cuda_runtime.h>
#include <cuda_fp16.h>
#include <cstdint>

// ---------------------------------------------------------------------------
// GraphSage (eval) on GB300 — round 17: round-15 structure (644.7us known
// good: fused intermediate + fused final layers, standalone aggregation)
// with an 8-edge-unrolled aggregation kernel (isolated change).
// ---------------------------------------------------------------------------

#define NMAX 50000
#define EMAX 1000000
#define FDIM 256
#define PADC 304
#define SCAN_B 1024
#define MAXBLK 64

// fp16 buffers (zero-initialized; pad columns never written)
__device__ __align__(16) __half g_h16[NMAX * FDIM];
__device__ __align__(16) __half g_hb16[NMAX * FDIM];
__device__ __align__(16) __half g_hagg16[NMAX * FDIM];
__device__ __align__(16) __half g_tmp16[NMAX * PADC];
__device__ __align__(16) __half g_emb16[(NMAX + 1) * 64];
__device__ __align__(16) __half g_c16[NMAX * PADC];
__device__ __align__(16) __half g_we16[256 * 64];
__device__ __align__(16) __half g_wp1[304 * PADC];
__device__ __align__(16) __half g_wp2[256 * PADC];
__device__ __align__(16) __half g_wc16[3 * 256 * 512];
__device__ __align__(16) __half g_wo1[2 * 256 * 256];
__device__ __align__(16) __half g_wo2[2 * 256 * 256];
// CSR
__device__ int g_deg[NMAX];
__device__ int g_rowoff[NMAX + 1];
__device__ int g_cursor[NMAX];
__device__ int g_adj[EMAX];
__device__ int g_bsum[MAXBLK];
__device__ int g_boff[MAXBLK];

// ---------------------------------------------------------------------------
struct StreamPack {
    cudaStream_t s1, s2;
    cudaEvent_t ev[8];
    StreamPack() {
        cudaStreamCreateWithFlags(&s1, cudaStreamNonBlocking);
        cudaStreamCreateWithFlags(&s2, cudaStreamNonBlocking);
        for (int i = 0; i < 8; i++)
            cudaEventCreateWithFlags(&ev[i], cudaEventDisableTiming);
    }
};
static StreamPack g_sp;

// ---------------------------------------------------------------------------
__global__ void cvt_all_kernel(
    const float* emb, const float* content, const float* W_exp,
    const float* W_p1, const float* W_p2, const float* W_conv,
    const float* Wo1, const float* Wo2,
    __half* d_emb, __half* d_c, __half* d_we, __half* d_wp1, __half* d_wp2,
    __half* d_wc, __half* d_wo1, __half* d_wo2,
    int N, int NC, int ED, int F, int L)
{
    const int s0 = (N + 1) * ED;
    const int s1 = N * NC;
    const int s2 = F * ED;
    const int s3 = NC * NC;
    const int s4 = F * NC;
    const int s5 = L * F * 2 * F;
    const int s6 = (L - 1) * F * F;
    const int s7 = (L - 1) * F * F;
    const int total = s0 + s1 + s2 + s3 + s4 + s5 + s6 + s7;
    for (int i = blockIdx.x * blockDim.x + threadIdx.x; i < total;
         i += gridDim.x * blockDim.x) {
        int j = i;
        if (j < s0) { d_emb[j] = __float2half_rn(emb[j]); continue; }
        j -= s0;
        if (j < s1) {
            int r = j / NC, c = j - r * NC;
            d_c[r * PADC + c] = __float2half_rn(content[j]);
            continue;
        }
        j -= s1;
        if (j < s2) { d_we[j] = __float2half_rn(W_exp[j]); continue; }
        j -= s2;
        if (j < s3) {
            int r = j / NC, c = j - r * NC;
            d_wp1[r * PADC + c] = __float2half_rn(W_p1[j]);
            continue;
        }
        j -= s3;
        if (j < s4) {
            int r = j / NC, c = j - r * NC;
            d_wp2[r * PADC + c] = __float2half_rn(W_p2[j]);
            continue;
        }
        j -= s4;
        if (j < s5) { d_wc[j] = __float2half_rn(W_conv[j]); continue; }
        j -= s5;
        if (j < s6) { d_wo1[j] = __float2half_rn(Wo1[j]); continue; }
        j -= s6;
        d_wo2[j] = __float2half_rn(Wo2[j]);
    }
}

// ---------------------------------------------------------------------------
// CSR build
__global__ void zero_deg_kernel(int n) {
    int i = blockIdx.x * blockDim.x + threadIdx.x;
    if (i < n) g_deg[i] = 0;
}
__global__ void count_deg_kernel(const int* __restrict__ dst, int E) {
    int i = blockIdx.x * blockDim.x + threadIdx.x;
    int stride = gridDim.x * blockDim.x;
    for (; i < E; i += stride) atomicAdd(&g_deg[dst[i]], 1);
}
__global__ void scan_reduce_kernel(int n) {
    __shared__ int ws[32];
    int t = threadIdx.x;
    int i = blockIdx.x * SCAN_B + t;
    int v = (i < n) ? g_deg[i] : 0;
    #pragma unroll
    for (int o = 16; o > 0; o >>= 1) v += __shfl_xor_sync(0xffffffffu, v, o);
    if ((t & 31) == 0) ws[t >> 5] = v;
    __syncthreads();
    if (t < 32) {
        int x = (t < (SCAN_B / 32)) ? ws[t] : 0;
        #pragma unroll
        for (int o = 16; o > 0; o >>= 1) x += __shfl_xor_sync(0xffffffffu, x, o);
        if (t == 0) g_bsum[blockIdx.x] = x;
    }
}
__global__ void scan_offsets_kernel(int nb, int n) {
    int acc = 0;
    for (int b = 0; b < nb; b++) { g_boff[b] = acc; acc += g_bsum[b]; }
    g_rowoff[n] = acc;
}
__global__ void scan_final_kernel(int n) {
    __shared__ int ws[32];
    int t = threadIdx.x;
    int i = blockIdx.x * SCAN_B + t;
    int v = (i < n) ? g_deg[i] : 0;
    int x = v;
    #pragma unroll
    for (int o = 1; o < 32; o <<= 1) {
        int y = __shfl_up_sync(0xffffffffu, x, o);
        if ((t & 31) >= o) x += y;
    }
    if ((t & 31) == 31) ws[t >> 5] = x;
    __syncthreads();
    if (t < 32) {
        int w = (t < (SCAN_B / 32)) ? ws[t] : 0;
        int xx = w;
        #pragma unroll
        for (int o = 1; o < 32; o <<= 1) {
            int y = __shfl_up_sync(0xffffffffu, xx, o);
            if (t >= o) xx += y;
        }
        ws[t] = xx - w;
    }
    __syncthreads();
    if (i < n) {
        int excl = x - v + ws[t >> 5] + g_boff[blockIdx.x];
        g_rowoff[i] = excl;
        g_cursor[i] = excl;
    }
}
__global__ void scatter_kernel(const int* __restrict__ src,
                               const int* __restrict__ dst, int E) {
    int i = blockIdx.x * blockDim.x + threadIdx.x;
    int stride = gridDim.x * blockDim.x;
    for (; i < E; i += stride) {
        int p = atomicAdd(&g_cursor[dst[i]], 1);
        g_adj[p] = src[i];
    }
}

// ---------------------------------------------------------------------------
// aggregate: hagg16[n] = fp16(mean of in-neighbor h rows); 8-edge unroll.
__global__ void aggregate_kernel(const __half* __restrict__ h, int N) {
    int node = blockIdx.x * blockDim.y + threadIdx.y;
    if (node >= N) return;
    int j = threadIdx.x;  // 0..63
    int beg = g_rowoff[node], end = g_rowoff[node + 1];
    float a0 = 0.f, a1 = 0.f, a2 = 0.f, a3 = 0.f;
    int e = beg;
    for (; e + 7 < end; e += 8) {
        int s0 = __ldg(&g_adj[e + 0]), s1 = __ldg(&g_adj[e + 1]);
        int s2 = __ldg(&g_adj[e + 2]), s3 = __ldg(&g_adj[e + 3]);
        int s4 = __ldg(&g_adj[e + 4]), s5 = __ldg(&g_adj[e + 5]);
        int s6 = __ldg(&g_adj[e + 6]), s7 = __ldg(&g_adj[e + 7]);
        uint2 u0 = *(const uint2*)&h[(size_t)s0 * FDIM + j * 4];
        uint2 u1 = *(const uint2*)&h[(size_t)s1 * FDIM + j * 4];
        uint2 u2 = *(const uint2*)&h[(size_t)s2 * FDIM + j * 4];
        uint2 u3 = *(const uint2*)&h[(size_t)s3 * FDIM + j * 4];
        uint2 u4 = *(const uint2*)&h[(size_t)s4 * FDIM + j * 4];
        uint2 u5 = *(const uint2*)&h[(size_t)s5 * FDIM + j * 4];
        uint2 u6 = *(const uint2*)&h[(size_t)s6 * FDIM + j * 4];
        uint2 u7 = *(const uint2*)&h[(size_t)s7 * FDIM + j * 4];
        float2 p;
        p = __half22float2(*(const __half2*)&u0.x); a0 += p.x; a1 += p.y;
        p = __half22float2(*(const __half2*)&u0.y); a2 += p.x; a3 += p.y;
        p = __half22float2(*(const __half2*)&u1.x); a0 += p.x; a1 += p.y;
        p = __half22float2(*(const __half2*)&u1.y); a2 += p.x; a3 += p.y;
        p = __half22float2(*(const __half2*)&u2.x); a0 += p.x; a1 += p.y;
        p = __half22float2(*(const __half2*)&u2.y); a2 += p.x; a3 += p.y;
        p = __half22float2(*(const __half2*)&u3.x); a0 += p.x; a1 += p.y;
        p = __half22float2(*(const __half2*)&u3.y); a2 += p.x; a3 += p.y;
        p = __half22float2(*(const __half2*)&u4.x); a0 += p.x; a1 += p.y;
        p = __half22float2(*(const __half2*)&u4.y); a2 += p.x; a3 += p.y;
        p = __half22float2(*(const __half2*)&u5.x); a0 += p.x; a1 += p.y;
        p = __half22float2(*(const __half2*)&u5.y); a2 += p.x; a3 += p.y;
        p = __half22float2(*(const __half2*)&u6.x); a0 += p.x; a1 += p.y;
        p = __half22float2(*(const __half2*)&u6.y); a2 += p.x; a3 += p.y;
        p = __half22float2(*(const __half2*)&u7.x); a0 += p.x; a1 += p.y;
        p = __half22float2(*(const __half2*)&u7.y); a2 += p.x; a3 += p.y;
    }
    for (; e < end; e++) {
        int s0 = __ldg(&g_adj[e]);
        uint2 u0 = *(const uint2*)&h[(size_t)s0 * FDIM + j * 4];
        float2 p;
        p = __half22float2(*(const __half2*)&u0.x); a0 += p.x; a1 += p.y;
        p = __half22float2(*(const __half2*)&u0.y); a2 += p.x; a3 += p.y;
    }
    int d = end - beg;
    float inv = 1.0f / (float)(d > 1 ? d : 1);
    uint2 o;
    *(__half2*)&o.x = __floats2half2_rn(a0 * inv, a1 * inv);
    *(__half2*)&o.y = __floats2half2_rn(a2 * inv, a3 * inv);
    *(uint2*)&g_hagg16[(size_t)node * FDIM + j * 4] = o;
}

// ---------------------------------------------------------------------------
__device__ __forceinline__ void mma_f16(float* c, const uint32_t* a,
                                        const uint32_t* b) {
    asm volatile(
        "mma.sync.aligned.m16n8k16.row.col.f32.f16.f16.f32 "
        "{%0,%1,%2,%3}, {%4,%5,%6,%7}, {%8,%9}, {%0,%1,%2,%3};"
        : "+f"(c[0]), "+f"(c[1]), "+f"(c[2]), "+f"(c[3])
        : "r"(a[0]), "r"(a[1]), "r"(a[2]), "r"(a[3]), "r"(b[0]), "r"(b[1]));
}
__device__ __forceinline__ void ldsm4(uint32_t* r, uint32_t addr) {
    asm volatile("ldmatrix.sync.aligned.m8n8.x4.shared.b16 {%0,%1,%2,%3}, [%4];"
                 : "=r"(r[0]), "=r"(r[1]), "=r"(r[2]), "=r"(r[3]) : "r"(addr));
}
__device__ __forceinline__ void cp16(uint32_t dst, const void* src, int nbytes) {
    asm volatile("cp.async.cg.shared.global [%0], [%1], 16, %2;"
                 :: "r"(dst), "l"(src), "r"(nbytes) : "memory");
}
__device__ __forceinline__ void cp_commit() {
    asm volatile("cp.async.commit_group;" ::: "memory");
}
__device__ __forceinline__ void cp_wait1() {
    asm volatile("cp.async.wait_group 1;" ::: "memory");
}

#define GBM 128
#define GBN 128
#define GBK 64
#define TILE_BYTES 16384
#define STAGE_BYTES (2 * TILE_BYTES)
#define NSTAGE 3

extern __shared__ __align__(16) char sm_raw[];

// ---------------------------------------------------------------------------
// Generic fp16 GEMM: used for emb/p1/p2 prologue.
__global__ __launch_bounds__(256, 2)
void gemm_f16(const __half* __restrict__ A, int lda,
              const int* __restrict__ gidx,
              const __half* __restrict__ W, int ldw,
              const float* __restrict__ bias,
              const __half* __restrict__ addsrc16,
              __half* __restrict__ C16, int ldc,
              int M, int Ncols, int K, int act)
{
    const int tid = threadIdx.x;
    const int wid = tid >> 5;
    const int lane = tid & 31;
    const int bm = blockIdx.x * GBM;
    const int bn = blockIdx.y * GBN;
    const int warp_m = (wid >> 2) * 64;
    const int warp_n = (wid & 3) * 32;

    const int ldRow = tid >> 1;
    const int kHalf = tid & 1;

    const bool aValid = (bm + ldRow < M);
    int aR = aValid ? (bm + ldRow) : 0;
    if (gidx) aR = __ldg(&gidx[aValid ? bm + ldRow : 0]);
    const __half* aBase = A + (size_t)aR * lda;
    const bool bValid = (bn + ldRow < Ncols);
    const __half* bBase = W + (size_t)(bValid ? bn + ldRow : 0) * ldw;

    const uint32_t smemBase = (uint32_t)__cvta_generic_to_shared(sm_raw);
    const int nCh = (K + GBK - 1) / GBK;
    const int ldSwz = (ldRow & 7);

    float acc[4][4][4];
    #pragma unroll
    for (int mt = 0; mt < 4; mt++)
        #pragma unroll
        for (int nt = 0; nt < 4; nt++)
            #pragma unroll
            for (int j = 0; j < 4; j++) acc[mt][nt][j] = 0.f;

    auto issueStage = [&](int ch, int stage) {
        if (ch < nCh) {
            const uint32_t aDst = smemBase + stage * STAGE_BYTES + ldRow * 128;
            const uint32_t bDst = aDst + TILE_BYTES;
            #pragma unroll
            for (int j = 0; j < 4; j++) {
                const int c = kHalf * 4 + j;
                const int k = ch * GBK + c * 8;
                const int rem = K - k;
                const int nb = (rem >= 8) ? 16 : (rem > 0 ? rem * 2 : 0);
                const uint32_t sw = (uint32_t)((c ^ ldSwz) << 4);
                cp16(aDst + sw, aBase + k, aValid ? nb : 0);
                cp16(bDst + sw, bBase + k, bValid ? nb : 0);
            }
        }
        cp_commit();
    };

    const int l8 = lane & 7;
    int aRowB[4], aSwz[4];
    #pragma unroll
    for (int mt = 0; mt < 4; mt++) {
        int row = warp_m + mt * 16 + l8 + ((lane >> 3) & 1) * 8;
        aRowB[mt] = row * 128;
        aSwz[mt] = row & 7;
    }
    const int aColAdd = lane >> 4;
    int bRowB[2], bSwz[2];
    #pragma unroll
    for (int pr = 0; pr < 2; pr++) {
        int row = warp_n + pr * 16 + l8 + ((lane >> 4) & 1) * 8;
        bRowB[pr] = row * 128;
        bSwz[pr] = row & 7;
    }
    const int bColAdd = (lane >> 3) & 1;

    auto computeStage = [&](int stage) {
        const uint32_t aTile = smemBase + stage * STAGE_BYTES;
        const uint32_t bTile = aTile + TILE_BYTES;
        #pragma unroll
        for (int ks = 0; ks < 4; ks++) {
            uint32_t af[4][4], bf[4][2];
            const int colA = ks * 2 + aColAdd;
            #pragma unroll
            for (int mt = 0; mt < 4; mt++)
                ldsm4(af[mt], aTile + aRowB[mt] + ((colA ^ aSwz[mt]) << 4));
            const int colB = ks * 2 + bColAdd;
            #pragma unroll
            for (int pr = 0; pr < 2; pr++) {
                uint32_t r[4];
                ldsm4(r, bTile + bRowB[pr] + ((colB ^ bSwz[pr]) << 4));
                bf[2 * pr][0] = r[0]; bf[2 * pr][1] = r[1];
                bf[2 * pr + 1][0] = r[2]; bf[2 * pr + 1][1] = r[3];
            }
            #pragma unroll
            for (int mt = 0; mt < 4; mt++)
                #pragma unroll
                for (int nt = 0; nt < 4; nt++)
                    mma_f16(acc[mt][nt], af[mt], bf[nt]);
        }
    };

    issueStage(0, 0);
    issueStage(1, 1);
    for (int ch = 0; ch < nCh; ch++) {
        cp_wait1();
        __syncthreads();
        computeStage(ch % NSTAGE);
        issueStage(ch + 2, (ch + 2) % NSTAGE);
    }

    #pragma unroll
    for (int mt = 0; mt < 4; mt++) {
        int row = bm + warp_m + mt * 16 + (lane >> 2);
        #pragma unroll
        for (int nt = 0; nt < 4; nt++) {
            int col = bn + warp_n + nt * 8 + 2 * (lane & 3);
            if (col >= Ncols) continue;
            float b0 = __ldg(&bias[col]);
            float b1 = __ldg(&bias[col + 1]);
            #pragma unroll
            for (int half = 0; half < 2; half++) {
                int r = row + half * 8;
                if (r >= M) continue;
                float v0 = acc[mt][nt][half * 2 + 0] + b0;
                float v1 = acc[mt][nt][half * 2 + 1] + b1;
                if (act) {
                    v0 = (v0 > 0.f) ? v0 : 0.1f * v0;
                    v1 = (v1 > 0.f) ? v1 : 0.1f * v1;
                }
                if (addsrc16) {
                    float2 s = __half22float2(
                        *(const __half2*)&addsrc16[(size_t)r * ldc + col]);
                    v0 += s.x; v1 += s.y;
                }
                *(__half2*)&C16[(size_t)r * ldc + col] =
                    __floats2half2_rn(v0, v1);
            }
        }
    }
}

// ---------------------------------------------------------------------------
// Fused layer machinery (128x256 full-row tile, 512 threads, 16 warps 32x64).
#define FTH 512
#define F_AB 16384
#define F_BB 32768
#define F_ST (F_AB + F_BB)
#define F_RING (3 * F_ST)             // 147456
#define F_TOFF F_RING
#define F_SMEM (F_RING + 65536)       // 212992 (intermediate layer)
#define FF_SMEM F_RING                // 147456 (final layer: ring only)

__global__ __launch_bounds__(FTH, 1)
void fused_layer(const __half* __restrict__ hin,
                 const __half* __restrict__ hagg,
                 const __half* __restrict__ Wc, const float* __restrict__ bc,
                 const __half* __restrict__ Wo1, const float* __restrict__ bo1,
                 const __half* __restrict__ Wo2, const float* __restrict__ bo2,
                 __half* __restrict__ hout, int M)
{
    const int tid = threadIdx.x;
    const int wid = tid >> 5;
    const int lane = tid & 31;
    const int bm = blockIdx.x * 128;
    const int warp_m = (wid >> 2) * 32;
    const int warp_n = (wid & 3) * 64;

    const int aRow = tid >> 2, aq = tid & 3;
    const int bRow = tid >> 1, bh = tid & 1;
    const bool aValid = (bm + aRow < M);
    const __half* aLo = hin  + (size_t)(aValid ? bm + aRow : 0) * 256;
    const __half* aHi = hagg + (size_t)(aValid ? bm + aRow : 0) * 256;
    const int aSwzL = aRow & 7, bSwzL = bRow & 7;

    const uint32_t smemBase = (uint32_t)__cvta_generic_to_shared(sm_raw);

    const int l8 = lane & 7;
    int aRowB[2], aSwz[2];
    #pragma unroll
    for (int mt = 0; mt < 2; mt++) {
        int row = warp_m + mt * 16 + l8 + ((lane >> 3) & 1) * 8;
        aRowB[mt] = row * 128;
        aSwz[mt] = row & 7;
    }
    const int aColAdd = lane >> 4;
    int bRowB[4], bSwz[4];
    #pragma unroll
    for (int pr = 0; pr < 4; pr++) {
        int row = warp_n + pr * 16 + l8 + ((lane >> 4) & 1) * 8;
        bRowB[pr] = row * 128;
        bSwz[pr] = row & 7;
    }
    const int bColAdd = (lane >> 3) & 1;

    float acc[2][8][4];
    auto zacc = [&] {
        #pragma unroll
        for (int mt = 0; mt < 2; mt++)
            #pragma unroll
            for (int nt = 0; nt < 8; nt++)
                #pragma unroll
                for (int j = 0; j < 4; j++) acc[mt][nt][j] = 0.f;
    };

    auto issueConv = [&](int ch) {
        const int stage = ch % 3;
        if (ch < 8) {
            const uint32_t aDst = smemBase + stage * F_ST + aRow * 128;
            #pragma unroll
            for (int j = 0; j < 2; j++) {
                const int c = aq * 2 + j;
                const int k = ch * 64 + c * 8;
                const __half* ap = (k < 256) ? (aLo + k) : (aHi + (k - 256));
                cp16(aDst + ((c ^ aSwzL) << 4), ap, aValid ? 16 : 0);
            }
            const uint32_t bDst = smemBase + stage * F_ST + F_AB + bRow * 128;
            #pragma unroll
            for (int j = 0; j < 4; j++) {
                const int c = bh * 4 + j;
                cp16(bDst + ((c ^ bSwzL) << 4),
                     Wc + (size_t)bRow * 512 + ch * 64 + c * 8, 16);
            }
        }
        cp_commit();
    };
    auto issueB = [&](const __half* W, int ch) {
        const int stage = ch % 3;
        if (ch < 4) {
            const uint32_t bDst = smemBase + stage * F_ST + F_AB + bRow * 128;
            #pragma unroll
            for (int j = 0; j < 4; j++) {
                const int c = bh * 4 + j;
                cp16(bDst + ((c ^ bSwzL) << 4),
                     W + (size_t)bRow * 256 + ch * 64 + c * 8, 16);
            }
        }
        cp_commit();
    };

    auto compute = [&](uint32_t aTile, uint32_t bTile) {
        #pragma unroll
        for (int ks = 0; ks < 4; ks++) {
            uint32_t af[2][4], bf[8][2];
            const int colA = ks * 2 + aColAdd;
            #pragma unroll
            for (int mt = 0; mt < 2; mt++)
                ldsm4(af[mt], aTile + aRowB[mt] + ((colA ^ aSwz[mt]) << 4));
            const int colB = ks * 2 + bColAdd;
            #pragma unroll
            for (int pr = 0; pr < 4; pr++) {
                uint32_t r[4];
                ldsm4(r, bTile + bRowB[pr] + ((colB ^ bSwz[pr]) << 4));
                bf[2 * pr][0] = r[0]; bf[2 * pr][1] = r[1];
                bf[2 * pr + 1][0] = r[2]; bf[2 * pr + 1][1] = r[3];
            }
            #pragma unroll
            for (int mt = 0; mt < 2; mt++)
                #pragma unroll
                for (int nt = 0; nt < 8; nt++)
                    mma_f16(acc[mt][nt], af[mt], bf[nt]);
        }
    };

    auto storeT = [&](int mt, int nt, int half, float v0, float v1) {
        int lr = warp_m + mt * 16 + (lane >> 2) + half * 8;
        int col = warp_n + nt * 8 + 2 * (lane & 3);
        int chunk = col >> 6;
        int c16 = (col >> 3) & 7;
        uint32_t off = (uint32_t)(F_TOFF + chunk * 16384 + lr * 128 +
                                  ((c16 ^ (lr & 7)) << 4) + (col & 7) * 2);
        *(__half2*)(sm_raw + off) = __floats2half2_rn(v0, v1);
    };

    // phase 0: conv (K=512)
    zacc();
    issueConv(0); issueConv(1);
    for (int ch = 0; ch < 8; ch++) {
        cp_wait1();
        __syncthreads();
        compute(smemBase + (ch % 3) * F_ST, smemBase + (ch % 3) * F_ST + F_AB);
        issueConv(ch + 2);
    }
    __syncthreads();

    float ssl[2][2] = {{0.f, 0.f}, {0.f, 0.f}};
    #pragma unroll
    for (int mt = 0; mt < 2; mt++)
        #pragma unroll
        for (int nt = 0; nt < 8; nt++) {
            int col = warp_n + nt * 8 + 2 * (lane & 3);
            float b0 = __ldg(&bc[col]);
            float b1 = __ldg(&bc[col + 1]);
            #pragma unroll
            for (int half = 0; half < 2; half++) {
                float v0 = acc[mt][nt][half * 2 + 0] + b0;
                float v1 = acc[mt][nt][half * 2 + 1] + b1;
                v0 = (v0 > 0.f) ? v0 : 0.1f * v0;
                v1 = (v1 > 0.f) ? v1 : 0.1f * v1;
                acc[mt][nt][half * 2 + 0] = v0;
                acc[mt][nt][half * 2 + 1] = v1;
                ssl[mt][half] += v0 * v0 + v1 * v1;
            }
        }
    #pragma unroll
    for (int mt = 0; mt < 2; mt++)
        #pragma unroll
        for (int half = 0; half < 2; half++) {
            float s = ssl[mt][half];
            s += __shfl_xor_sync(0xffffffffu, s, 1);
            s += __shfl_xor_sync(0xffffffffu, s, 2);
            ssl[mt][half] = s;
        }
    float* part = (float*)sm_raw;
    float* invArr = (float*)(sm_raw + 2048);
    if ((lane & 3) == 0) {
        #pragma unroll
        for (int mt = 0; mt < 2; mt++)
            #pragma unroll
            for (int half = 0; half < 2; half++) {
                int lr = warp_m + mt * 16 + (lane >> 2) + half * 8;
                part[lr * 4 + (wid & 3)] = ssl[mt][half];
            }
    }
    __syncthreads();
    if (tid < 128) {
        float s = part[tid * 4] + part[tid * 4 + 1] +
                  part[tid * 4 + 2] + part[tid * 4 + 3];
        invArr[tid] = 1.0f / fmaxf(sqrtf(s), 1e-6f);
    }
    __syncthreads();
    float invs[2][2];
    #pragma unroll
    for (int mt = 0; mt < 2; mt++)
        #pragma unroll
        for (int half = 0; half < 2; half++)
            invs[mt][half] = invArr[warp_m + mt * 16 + (lane >> 2) + half * 8];
    #pragma unroll
    for (int mt = 0; mt < 2; mt++)
        #pragma unroll
        for (int nt = 0; nt < 8; nt++)
            #pragma unroll
            for (int half = 0; half < 2; half++)
                storeT(mt, nt, half, acc[mt][nt][half * 2], acc[mt][nt][half * 2 + 1]);
    issueB(Wo1, 0); issueB(Wo1, 1);
    __syncthreads();

    // phase 1: Wo1
    zacc();
    for (int ch = 0; ch < 4; ch++) {
        cp_wait1();
        __syncthreads();
        compute(smemBase + F_TOFF + ch * 16384,
                smemBase + (ch % 3) * F_ST + F_AB);
        issueB(Wo1, ch + 2);
    }
    __syncthreads();
    #pragma unroll
    for (int mt = 0; mt < 2; mt++)
        #pragma unroll
        for (int nt = 0; nt < 8; nt++) {
            int col = warp_n + nt * 8 + 2 * (lane & 3);
            float b0 = __ldg(&bo1[col]);
            float b1 = __ldg(&bo1[col + 1]);
            #pragma unroll
            for (int half = 0; half < 2; half++) {
                float v0 = acc[mt][nt][half * 2 + 0] * invs[mt][half] + b0;
                float v1 = acc[mt][nt][half * 2 + 1] * invs[mt][half] + b1;
                v0 = (v0 > 0.f) ? v0 : 0.1f * v0;
                v1 = (v1 > 0.f) ? v1 : 0.1f * v1;
                storeT(mt, nt, half, v0, v1);
            }
        }
    issueB(Wo2, 0); issueB(Wo2, 1);
    __syncthreads();

    // phase 2: Wo2
    zacc();
    for (int ch = 0; ch < 4; ch++) {
        cp_wait1();
        __syncthreads();
        compute(smemBase + F_TOFF + ch * 16384,
                smemBase + (ch % 3) * F_ST + F_AB);
        issueB(Wo2, ch + 2);
    }
    #pragma unroll
    for (int mt = 0; mt < 2; mt++) {
        #pragma unroll
        for (int half = 0; half < 2; half++) {
            int r = bm + warp_m + mt * 16 + (lane >> 2) + half * 8;
            if (r >= M) continue;
            #pragma unroll
            for (int nt = 0; nt < 8; nt++) {
                int col = warp_n + nt * 8 + 2 * (lane & 3);
                float v0 = acc[mt][nt][half * 2 + 0] + __ldg(&bo2[col]);
                float v1 = acc[mt][nt][half * 2 + 1] + __ldg(&bo2[col + 1]);
                *(__half2*)&hout[(size_t)r * 256 + col] =
                    __floats2half2_rn(v0, v1);
            }
        }
    }
}

// ---------------------------------------------------------------------------
// Fused FINAL layer: out = l2norm_row([h|hagg] @ Wc^T + bc), fp32 out.
__global__ __launch_bounds__(FTH, 1)
void fused_final(const __half* __restrict__ hin,
                 const __half* __restrict__ hagg,
                 const __half* __restrict__ Wc, const float* __restrict__ bc,
                 float* __restrict__ out, int M)
{
    const int tid = threadIdx.x;
    const int wid = tid >> 5;
    const int lane = tid & 31;
    const int bm = blockIdx.x * 128;
    const int warp_m = (wid >> 2) * 32;
    const int warp_n = (wid & 3) * 64;

    const int aRow = tid >> 2, aq = tid & 3;
    const int bRow = tid >> 1, bh = tid & 1;
    const bool aValid = (bm + aRow < M);
    const __half* aLo = hin  + (size_t)(aValid ? bm + aRow : 0) * 256;
    const __half* aHi = hagg + (size_t)(aValid ? bm + aRow : 0) * 256;
    const int aSwzL = aRow & 7, bSwzL = bRow & 7;

    const uint32_t smemBase = (uint32_t)__cvta_generic_to_shared(sm_raw);

    const int l8 = lane & 7;
    int aRowB[2], aSwz[2];
    #pragma unroll
    for (int mt = 0; mt < 2; mt++) {
        int row = warp_m + mt * 16 + l8 + ((lane >> 3) & 1) * 8;
        aRowB[mt] = row * 128;
        aSwz[mt] = row & 7;
    }
    const int aColAdd = lane >> 4;
    int bRowB[4], bSwz[4];
    #pragma unroll
    for (int pr = 0; pr < 4; pr++) {
        int row = warp_n + pr * 16 + l8 + ((lane >> 4) & 1) * 8;
        bRowB[pr] = row * 128;
        bSwz[pr] = row & 7;
    }
    const int bColAdd = (lane >> 3) & 1;

    float acc[2][8][4];
    #pragma unroll
    for (int mt = 0; mt < 2; mt++)
        #pragma unroll
        for (int nt = 0; nt < 8; nt++)
            #pragma unroll
            for (int j = 0; j < 4; j++) acc[mt][nt][j] = 0.f;

    auto issueConv = [&](int ch) {
        const int stage = ch % 3;
        if (ch < 8) {
            const uint32_t aDst = smemBase + stage * F_ST + aRow * 128;
            #pragma unroll
            for (int j = 0; j < 2; j++) {
                const int c = aq * 2 + j;
                const int k = ch * 64 + c * 8;
                const __half* ap = (k < 256) ? (aLo + k) : (aHi + (k - 256));
                cp16(aDst + ((c ^ aSwzL) << 4), ap, aValid ? 16 : 0);
            }
            const uint32_t bDst = smemBase + stage * F_ST + F_AB + bRow * 128;
            #pragma unroll
            for (int j = 0; j < 4; j++) {
                const int c = bh * 4 + j;
                cp16(bDst + ((c ^ bSwzL) << 4),
                     Wc + (size_t)bRow * 512 + ch * 64 + c * 8, 16);
            }
        }
        cp_commit();
    };

    auto compute = [&](uint32_t aTile, uint32_t bTile) {
        #pragma unroll
        for (int ks = 0; ks < 4; ks++) {
            uint32_t af[2][4], bf[8][2];
            const int colA = ks * 2 + aColAdd;
            #pragma unroll
            for (int mt = 0; mt < 2; mt++)
                ldsm4(af[mt], aTile + aRowB[mt] + ((colA ^ aSwz[mt]) << 4));
            const int colB = ks * 2 + bColAdd;
            #pragma unroll
            for (int pr = 0; pr < 4; pr++) {
                uint32_t r[4];
                ldsm4(r, bTile + bRowB[pr] + ((colB ^ bSwz[pr]) << 4));
                bf[2 * pr][0] = r[0]; bf[2 * pr][1] = r[1];
                bf[2 * pr + 1][0] = r[2]; bf[2 * pr + 1][1] = r[3];
            }
            #pragma unroll
            for (int mt = 0; mt < 2; mt++)
                #pragma unroll
                for (int nt = 0; nt < 8; nt++)
                    mma_f16(acc[mt][nt], af[mt], bf[nt]);
        }
    };

    issueConv(0); issueConv(1);
    for (int ch = 0; ch < 8; ch++) {
        cp_wait1();
        __syncthreads();
        compute(smemBase + (ch % 3) * F_ST, smemBase + (ch % 3) * F_ST + F_AB);
        issueConv(ch + 2);
    }
    __syncthreads();

    // epilogue: bias (no act), row sumsq in-CTA, write normalized fp32
    float ssl[2][2] = {{0.f, 0.f}, {0.f, 0.f}};
    #pragma unroll
    for (int mt = 0; mt < 2; mt++)
        #pragma unroll
        for (int nt = 0; nt < 8; nt++) {
            int col = warp_n + nt * 8 + 2 * (lane & 3);
            float b0 = __ldg(&bc[col]);
            float b1 = __ldg(&bc[col + 1]);
            #pragma unroll
            for (int half = 0; half < 2; half++) {
                float v0 = acc[mt][nt][half * 2 + 0] + b0;
                float v1 = acc[mt][nt][half * 2 + 1] + b1;
                acc[mt][nt][half * 2 + 0] = v0;
                acc[mt][nt][half * 2 + 1] = v1;
                ssl[mt][half] += v0 * v0 + v1 * v1;
            }
        }
    #pragma unroll
    for (int mt = 0; mt < 2; mt++)
        #pragma unroll
        for (int half = 0; half < 2; half++) {
            float s = ssl[mt][half];
            s += __shfl_xor_sync(0xffffffffu, s, 1);
            s += __shfl_xor_sync(0xffffffffu, s, 2);
            ssl[mt][half] = s;
        }
    float* part = (float*)sm_raw;
    float* invArr = (float*)(sm_raw + 2048);
    if ((lane & 3) == 0) {
        #pragma unroll
        for (int mt = 0; mt < 2; mt++)
            #pragma unroll
            for (int half = 0; half < 2; half++) {
                int lr = warp_m + mt * 16 + (lane >> 2) + half * 8;
                part[lr * 4 + (wid & 3)] = ssl[mt][half];
            }
    }
    __syncthreads();
    if (tid < 128) {
        float s = part[tid * 4] + part[tid * 4 + 1] +
                  part[tid * 4 + 2] + part[tid * 4 + 3];
        invArr[tid] = 1.0f / fmaxf(sqrtf(s), 1e-6f);
    }
    __syncthreads();
    #pragma unroll
    for (int mt = 0; mt < 2; mt++) {
        #pragma unroll
        for (int half = 0; half < 2; half++) {
            int lr = warp_m + mt * 16 + (lane >> 2) + half * 8;
            int r = bm + lr;
            if (r >= M) continue;
            float inv = invArr[lr];
            #pragma unroll
            for (int nt = 0; nt < 8; nt++) {
                int col = warp_n + nt * 8 + 2 * (lane & 3);
                *(float2*)&out[(size_t)r * 256 + col] =
                    make_float2(acc[mt][nt][half * 2] * inv,
                                acc[mt][nt][half * 2 + 1] * inv);
            }
        }
    }
}

// ---------------------------------------------------------------------------
extern "C" void kernel_launch(void* const* d_in, const int* in_sizes, int n_in,
                              void* d_out, int out_size) {
    const int*   node_ids = (const int*)  d_in[0];
    const float* content  = (const float*)d_in[1];
    const int*   src      = (const int*)  d_in[2];
    const int*   dst      = (const int*)  d_in[3];
    const float* emb      = (const float*)d_in[4];
    const float* W_exp    = (const float*)d_in[5];
    const float* b_exp    = (const float*)d_in[6];
    const float* W_p1     = (const float*)d_in[7];
    const float* b_p1     = (const float*)d_in[8];
    const float* W_p2     = (const float*)d_in[9];
    const float* b_p2     = (const float*)d_in[10];
    const float* W_conv   = (const float*)d_in[11];
    const float* b_conv   = (const float*)d_in[12];
    const float* Wo1      = (const float*)d_in[13];
    const float* bo1      = (const float*)d_in[14];
    const float* Wo2      = (const float*)d_in[15];
    const float* bo2      = (const float*)d_in[16];
    float* out = (float*)d_out;

    const int N  = in_sizes[0];
    const int E  = in_sizes[2];
    const int NC = in_sizes[1] / N;                 // 300
    const int ED = in_sizes[4] / (N + 1);           // 64
    const int F  = in_sizes[5] / ED;                // 256
    const int L  = in_sizes[11] / (F * 2 * F);      // 3

    __half *p_h16, *p_hb16, *p_hagg16, *p_tmp16, *p_emb16, *p_c16;
    __half *p_we, *p_wp1, *p_wp2, *p_wc, *p_wo1, *p_wo2;
    cudaGetSymbolAddress((void**)&p_h16, g_h16);
    cudaGetSymbolAddress((void**)&p_hb16, g_hb16);
    cudaGetSymbolAddress((void**)&p_hagg16, g_hagg16);
    cudaGetSymbolAddress((void**)&p_tmp16, g_tmp16);
    cudaGetSymbolAddress((void**)&p_emb16, g_emb16);
    cudaGetSymbolAddress((void**)&p_c16, g_c16);
    cudaGetSymbolAddress((void**)&p_we, g_we16);
    cudaGetSymbolAddress((void**)&p_wp1, g_wp1);
    cudaGetSymbolAddress((void**)&p_wp2, g_wp2);
    cudaGetSymbolAddress((void**)&p_wc, g_wc16);
    cudaGetSymbolAddress((void**)&p_wo1, g_wo1);
    cudaGetSymbolAddress((void**)&p_wo2, g_wo2);

    const int SMEM = NSTAGE * STAGE_BYTES;  // 98304
    cudaFuncSetAttribute(gemm_f16, cudaFuncAttributeMaxDynamicSharedMemorySize, SMEM);
    cudaFuncSetAttribute(fused_layer, cudaFuncAttributeMaxDynamicSharedMemorySize, F_SMEM);
    cudaFuncSetAttribute(fused_final, cudaFuncAttributeMaxDynamicSharedMemorySize, FF_SMEM);

    cudaStream_t s1 = g_sp.s1, s2 = g_sp.s2;
    cudaEvent_t* ev = g_sp.ev;

    // ---- fork CSR chain to s1 ----
    cudaEventRecord(ev[0], 0);
    cudaStreamWaitEvent(s1, ev[0], 0);
    const int nb = (N + SCAN_B - 1) / SCAN_B;
    zero_deg_kernel<<<(N + 255) / 256, 256, 0, s1>>>(N);
    count_deg_kernel<<<1024, 256, 0, s1>>>(dst, E);
    scan_reduce_kernel<<<nb, SCAN_B, 0, s1>>>(N);
    scan_offsets_kernel<<<1, 1, 0, s1>>>(nb, N);
    scan_final_kernel<<<nb, SCAN_B, 0, s1>>>(N);
    scatter_kernel<<<1024, 256, 0, s1>>>(src, dst, E);
    cudaEventRecord(ev[1], s1);

    // ---- conversions on stream0 ----
    cvt_all_kernel<<<2048, 256>>>(emb, content, W_exp, W_p1, W_p2, W_conv,
                                  Wo1, Wo2, p_emb16, p_c16, p_we, p_wp1,
                                  p_wp2, p_wc, p_wo1, p_wo2, N, NC, ED, F, L);

    const int gmx = (N + GBM - 1) / GBM;
    auto gy = [](int n) { return (n + GBN - 1) / GBN; };

    // ---- emb GEMM on s2 -> fp16 scratch (hb16) ----
    cudaEventRecord(ev[2], 0);
    cudaStreamWaitEvent(s2, ev[2], 0);
    gemm_f16<<<dim3(gmx, gy(F)), 256, SMEM, s2>>>(
        p_emb16, ED, node_ids, p_we, ED, b_exp, nullptr,
        p_hb16, F, N, F, ED, 1);
    cudaEventRecord(ev[3], s2);

    gemm_f16<<<dim3(gmx, gy(NC)), 256, SMEM>>>(
        p_c16, PADC, nullptr, p_wp1, PADC, b_p1, nullptr,
        p_tmp16, PADC, N, NC, PADC, 1);
    cudaStreamWaitEvent(0, ev[3], 0);
    gemm_f16<<<dim3(gmx, gy(F)), 256, SMEM>>>(
        p_tmp16, PADC, nullptr, p_wp2, PADC, b_p2, p_hb16,
        p_h16, F, N, F, PADC, 1);

    cudaStreamWaitEvent(0, ev[1], 0);

    // ---- layers (h ping-pong between h16 and hb16) ----
    __half* hbuf[2] = {p_h16, p_hb16};
    int cur = 0;
    for (int i = 0; i < L; i++) {
        dim3 aggBlk(64, 4);
        aggregate_kernel<<<(N + 3) / 4, aggBlk>>>(hbuf[cur], N);

        if (i < L - 1) {
            fused_layer<<<gmx, FTH, F_SMEM>>>(
                hbuf[cur], p_hagg16,
                p_wc + (size_t)i * F * 2 * F, b_conv + (size_t)i * F,
                p_wo1 + (size_t)i * F * F, bo1 + (size_t)i * F,
                p_wo2 + (size_t)i * F * F, bo2 + (size_t)i * F,
                hbuf[1 - cur], N);
            cur ^= 1;
        } else {
            fused_final<<<gmx, FTH, FF_SMEM>>>(
                hbuf[cur], p_hagg16,
                p_wc + (size_t)i * F * 2 * F, b_conv + (size_t)i * F,
                out, N);
        }
    }
}